// round 16
// baseline (speedup 1.0000x reference)
#include <cuda_runtime.h>
#include <math.h>

#define MASK_ID   103
#define L_SEQ     128
#define SMOOTH_F  0.2f
#define MAXN      4096
#define NT        256
#define SHIFT     8.0f

// ---------------- scratch (no allocation allowed) ----------------
__device__ float g_mle[MAXN];
__device__ float g_wgt[MAXN];
__device__ float g_unl[MAXN];
__device__ int   g_mrow[MAXN];
__device__ int   g_mcol[MAXN];
__device__ int   g_flag;        // 0 -> mask table not ready
__device__ int   g_done;        // completed row blocks (ticket counter)

// ---------------- single fused kernel, grid = N+1 ----------------
// Block 0 ONLY builds the mask-position table (~6us) and exits. Blocks 1..N
// process pred row (bid-1) with NT=256 (8 CTAs/SM = 8 independent DRAM
// streams per SM vs 4 before — testing whether concurrent-stream count, not
// per-thread MLP, limits DRAM page parallelism; all 4-CTA configs pinned at
// ~4.1 TB/s). Last row block (atomic ticket) inlines the final reduction in
// a fixed order and resets flags for graph replay.
__global__ __launch_bounds__(NT)
void row_kernel(const float* __restrict__ pred,
                const int*   __restrict__ target,
                const int*   __restrict__ tok_ids,
                const float* __restrict__ attn,
                const float* __restrict__ weight,
                const int*   __restrict__ masked,
                float* __restrict__ out,
                int C, int N, int BL, int out_size)
{
    const int tid  = threadIdx.x;
    const int lane = tid & 31;
    const int wid  = tid >> 5;

    __shared__ float red_a[NT / 32];
    __shared__ float red_b[NT / 32];
    __shared__ int   wtot[32];
    __shared__ int   sbase;
    __shared__ float sh_ai[L_SEQ];
    __shared__ float sh_negw[L_SEQ];
    __shared__ float sh_negc[L_SEQ];
    __shared__ float sh_w[L_SEQ];
    __shared__ int   sh_cand[L_SEQ];
    __shared__ float sh_logZ, sh_rowsum;
    __shared__ int   sh_last;

    // ================= block 0: build mask-position table, then exit ========
    if (blockIdx.x == 0) {
        if (tid == 0) sbase = 0;
        __syncthreads();
        for (int base = 0; base < BL; base += NT * 8) {
            const int start = base + tid * 8;
            int v[8];
            if (start + 8 <= BL) {
                int4 a = ((const int4*)(masked + start))[0];
                int4 b = ((const int4*)(masked + start))[1];
                v[0]=a.x; v[1]=a.y; v[2]=a.z; v[3]=a.w;
                v[4]=b.x; v[5]=b.y; v[6]=b.z; v[7]=b.w;
            } else {
                #pragma unroll
                for (int j = 0; j < 8; j++)
                    v[j] = (start + j < BL) ? masked[start + j] : (MASK_ID + 1);
            }
            int hits[8];
            int cnt = 0;
            #pragma unroll
            for (int j = 0; j < 8; j++)
                if (v[j] == MASK_ID) hits[cnt++] = start + j;

            int inc = cnt;
            #pragma unroll
            for (int o = 1; o < 32; o <<= 1) {
                int t = __shfl_up_sync(0xffffffffu, inc, o);
                if (lane >= o) inc += t;
            }
            if (lane == 31) wtot[wid] = inc;
            __syncthreads();
            if (wid == 0) {
                int t = (lane < NT / 32) ? wtot[lane] : 0;
                #pragma unroll
                for (int o = 1; o < 32; o <<= 1) {
                    int u = __shfl_up_sync(0xffffffffu, t, o);
                    if (lane >= o) t += u;
                }
                if (lane < NT / 32) wtot[lane] = t;
            }
            __syncthreads();
            int excl = sbase + inc - cnt + (wid > 0 ? wtot[wid - 1] : 0);
            for (int k = 0; k < cnt; k++) {
                int o = excl + k;
                if (o < N && o < MAXN) {
                    int pos = hits[k];
                    g_mrow[o] = pos >> 7;
                    g_mcol[o] = pos & (L_SEQ - 1);
                }
            }
            __syncthreads();
            if (tid == 0) sbase += wtot[NT / 32 - 1];
            __syncthreads();
        }
        __threadfence();
        __syncthreads();
        if (tid == 0) atomicExch(&g_flag, 1);
        return;
    }

    // ================= row blocks =================
    const int r = blockIdx.x - 1;
    if (r >= N) return;
    const float* __restrict__ row = pred + (size_t)r * (size_t)C;

    // ---- streaming branchless shifted logsumexp + plain sum ----
    // float4 via __ldcs (evict-first), unrolled x4 (MLP=4).
    float s0 = 0.f, s1 = 0.f, s2 = 0.f, s3 = 0.f;
    float m0 = 0.f, m1 = 0.f, m2 = 0.f, m3 = 0.f;

    const int head = (int)(((16u - ((unsigned)(size_t)row & 15u)) & 15u) >> 2);
    if (tid < head) {
        float x = row[tid];
        s0 += __expf(x - SHIFT); m0 += x;
    }
    const float4* __restrict__ r4 = (const float4*)(row + head);
    const int n4   = (C - head) >> 2;
    const int tail = C - head - (n4 << 2);
    int i = tid;
    for (; i + 3 * NT < n4; i += 4 * NT) {
        float4 v0 = __ldcs(r4 + i);
        float4 v1 = __ldcs(r4 + i + NT);
        float4 v2 = __ldcs(r4 + i + 2 * NT);
        float4 v3 = __ldcs(r4 + i + 3 * NT);
        s0 += __expf(v0.x - SHIFT); m0 += v0.x;
        s1 += __expf(v0.y - SHIFT); m1 += v0.y;
        s2 += __expf(v0.z - SHIFT); m2 += v0.z;
        s3 += __expf(v0.w - SHIFT); m3 += v0.w;
        s0 += __expf(v1.x - SHIFT); m0 += v1.x;
        s1 += __expf(v1.y - SHIFT); m1 += v1.y;
        s2 += __expf(v1.z - SHIFT); m2 += v1.z;
        s3 += __expf(v1.w - SHIFT); m3 += v1.w;
        s0 += __expf(v2.x - SHIFT); m0 += v2.x;
        s1 += __expf(v2.y - SHIFT); m1 += v2.y;
        s2 += __expf(v2.z - SHIFT); m2 += v2.z;
        s3 += __expf(v2.w - SHIFT); m3 += v2.w;
        s0 += __expf(v3.x - SHIFT); m0 += v3.x;
        s1 += __expf(v3.y - SHIFT); m1 += v3.y;
        s2 += __expf(v3.z - SHIFT); m2 += v3.z;
        s3 += __expf(v3.w - SHIFT); m3 += v3.w;
    }
    for (; i < n4; i += NT) {
        float4 v = __ldcs(r4 + i);
        s0 += __expf(v.x - SHIFT); m0 += v.x;
        s1 += __expf(v.y - SHIFT); m1 += v.y;
        s2 += __expf(v.z - SHIFT); m2 += v.z;
        s3 += __expf(v.w - SHIFT); m3 += v.w;
    }
    if (tid < tail) {
        float x = row[head + (n4 << 2) + tid];
        s0 += __expf(x - SHIFT); m0 += x;
    }
    float s   = (s0 + s1) + (s2 + s3);
    float sum = (m0 + m1) + (m2 + m3);

    #pragma unroll
    for (int o = 16; o > 0; o >>= 1) {
        s   += __shfl_xor_sync(0xffffffffu, s, o);
        sum += __shfl_xor_sync(0xffffffffu, sum, o);
    }
    if (lane == 0) { red_a[wid] = s; red_b[wid] = sum; }

    // ---- wait for mask table (released ~6us in; we arrive much later) ----
    if (tid == 0) {
        while (atomicAdd(&g_flag, 0) == 0) __nanosleep(64);
    }
    __syncthreads();

    if (wid == 0) {
        float a = (lane < NT / 32) ? red_a[lane] : 0.f;
        float d = (lane < NT / 32) ? red_b[lane] : 0.f;
        #pragma unroll
        for (int o = 16; o > 0; o >>= 1) {
            a += __shfl_xor_sync(0xffffffffu, a, o);
            d += __shfl_xor_sync(0xffffffffu, d, o);
        }
        if (lane == 0) { sh_logZ = SHIFT + logf(a); sh_rowsum = d; }
    }

    const int b = g_mrow[r];
    const int c = g_mcol[r];

    // ---- per-position negative-target weights (faithful to reference) ----
    if (tid < L_SEQ) {
        float a = attn[b * L_SEQ + tid];
        float t = (float)tok_ids[b * L_SEQ + tid];
        sh_ai[tid] = a * t;
        sh_w[tid]  = a;
    }
    __syncthreads();
    const float center = sh_ai[c];
    if (tid < L_SEQ) {
        float a    = sh_w[tid];
        float negw = a - ((sh_ai[tid] == center) ? 1.f : 0.f);
        sh_negw[tid] = negw;
        sh_negc[tid] = sh_ai[tid] * negw;
    }
    __syncthreads();
    if (tid < L_SEQ) {
        float wfin, candf;
        if (c > 0) {
            float prev = sh_negc[c - 1];
            int   jm   = (tid - 1 + L_SEQ) & (L_SEQ - 1);
            float nm   = (sh_negc[jm] == prev) ? 1.f : 0.f;
            float nw2  = sh_negw[tid] * (1.f + nm);
            wfin  = nw2;
            candf = sh_ai[tid] * ((nw2 != 0.f) ? 1.f : 0.f);
        } else {
            wfin  = sh_negw[tid];
            candf = sh_negc[tid];
        }
        sh_w[tid]    = wfin;
        sh_cand[tid] = (int)candf;
    }
    __syncthreads();

    const float logZ = sh_logZ;

    // ---- unlikelihood gather (PRECISION-CRITICAL: precise expf/logf) ----
    float u = 0.f;
    if (tid < L_SEQ) {
        float w = sh_w[tid];
        if (w != 0.f) {
            int   idx = sh_cand[tid];
            float lp  = row[idx] - logZ;
            float omp = fmaxf(1.f - expf(lp), 1e-5f);
            u = -logf(omp) * w;
        }
    }
    #pragma unroll
    for (int o = 16; o > 0; o >>= 1)
        u += __shfl_xor_sync(0xffffffffu, u, o);
    if (lane == 0) red_a[wid] = u;
    __syncthreads();

    if (tid == 0) {
        float ut = 0.f;
        #pragma unroll
        for (int k = 0; k < NT / 32; k++) ut += red_a[k];
        g_unl[r] = ut;
        int   tgt = target[r];
        float lpt = row[tgt] - logZ;
        float sumlogp = sh_rowsum - (float)C * logZ;
        float epsw = SMOOTH_F / (float)(C - 1);
        float conf = 1.f - SMOOTH_F;
        float l = -(epsw * sumlogp + (conf - epsw) * lpt);
        float w = weight[tgt];
        g_mle[r] = l * w;
        g_wgt[r] = w;
        __threadfence();
        int ticket = atomicAdd(&g_done, 1);
        sh_last = (ticket == N - 1) ? 1 : 0;
    }
    __syncthreads();

    // ================= last row block: inline final reduction =================
    if (sh_last) {
        __threadfence();  // acquire: all g_* writes visible
        __shared__ double sm[NT], sw[NT], su[NT];
        double a = 0.0, w = 0.0, u2 = 0.0;
        for (int k = tid; k < N; k += NT) {
            a  += (double)g_mle[k];
            w  += (double)g_wgt[k];
            u2 += (double)g_unl[k];
        }
        sm[tid] = a; sw[tid] = w; su[tid] = u2;
        __syncthreads();
        for (int o = NT >> 1; o > 0; o >>= 1) {
            if (tid < o) { sm[tid] += sm[tid + o]; sw[tid] += sw[tid + o]; su[tid] += su[tid + o]; }
            __syncthreads();
        }
        if (tid == 0) {
            double mle  = sm[0] / sw[0];
            double unl  = su[0] / (double)N;
            double loss = mle + unl;   // RANK_ALPHA = 1.0
            if (out_size > 0) out[0] = (float)loss;
            if (out_size > 1) out[1] = (float)mle;
            if (out_size > 2) out[2] = (float)unl;
            for (int k = 3; k < out_size; k++) out[k] = 0.f;
            g_flag = 0;
            g_done = 0;
        }
    }
}

// ---------------- launch ----------------
extern "C" void kernel_launch(void* const* d_in, const int* in_sizes, int n_in,
                              void* d_out, int out_size)
{
    const float* pred   = (const float*)d_in[0];
    const int*   target = (const int*)  d_in[1];
    const int*   tok    = (const int*)  d_in[2];
    const float* attn   = (const float*)d_in[3];
    const int*   masked = (const int*)  d_in[4];
    const float* weight = (const float*)d_in[5];

    int N  = in_sizes[1];
    int C  = in_sizes[5];
    int BL = in_sizes[4];

    row_kernel<<<N + 1, NT>>>(pred, target, tok, attn, weight, masked,
                              (float*)d_out, C, N, BL, out_size);
}

// round 17
// speedup vs baseline: 1.0328x; 1.0328x over previous
#include <cuda_runtime.h>
#include <math.h>

#define MASK_ID   103
#define L_SEQ     128
#define SMOOTH_F  0.2f
#define MAXN      4096
#define NT        256
#define SHIFT     8.0f

// ---------------- scratch (no allocation allowed) ----------------
__device__ float g_mle[MAXN];
__device__ float g_wgt[MAXN];
__device__ float g_unl[MAXN];
__device__ int   g_mrow[MAXN];
__device__ int   g_mcol[MAXN];
__device__ int   g_flag;        // 0 -> mask table not ready
__device__ int   g_done;        // completed row blocks (ticket counter)

// ---------------- single fused kernel, grid = N+1 ----------------
// Block 0 ONLY builds the mask-position table (~6us) and exits. Blocks 1..N
// process pred row (bid-1) with NT=256 (8 CTAs/SM = 8 independent DRAM
// streams per SM vs 4 before — testing whether concurrent-stream count, not
// per-thread MLP, limits DRAM page parallelism; all 4-CTA configs pinned at
// ~4.1 TB/s). Last row block (atomic ticket) inlines the final reduction in
// a fixed order and resets flags for graph replay.
__global__ __launch_bounds__(NT)
void row_kernel(const float* __restrict__ pred,
                const int*   __restrict__ target,
                const int*   __restrict__ tok_ids,
                const float* __restrict__ attn,
                const float* __restrict__ weight,
                const int*   __restrict__ masked,
                float* __restrict__ out,
                int C, int N, int BL, int out_size)
{
    const int tid  = threadIdx.x;
    const int lane = tid & 31;
    const int wid  = tid >> 5;

    __shared__ float red_a[NT / 32];
    __shared__ float red_b[NT / 32];
    __shared__ int   wtot[32];
    __shared__ int   sbase;
    __shared__ float sh_ai[L_SEQ];
    __shared__ float sh_negw[L_SEQ];
    __shared__ float sh_negc[L_SEQ];
    __shared__ float sh_w[L_SEQ];
    __shared__ int   sh_cand[L_SEQ];
    __shared__ float sh_logZ, sh_rowsum;
    __shared__ int   sh_last;

    // ================= block 0: build mask-position table, then exit ========
    if (blockIdx.x == 0) {
        if (tid == 0) sbase = 0;
        __syncthreads();
        for (int base = 0; base < BL; base += NT * 8) {
            const int start = base + tid * 8;
            int v[8];
            if (start + 8 <= BL) {
                int4 a = ((const int4*)(masked + start))[0];
                int4 b = ((const int4*)(masked + start))[1];
                v[0]=a.x; v[1]=a.y; v[2]=a.z; v[3]=a.w;
                v[4]=b.x; v[5]=b.y; v[6]=b.z; v[7]=b.w;
            } else {
                #pragma unroll
                for (int j = 0; j < 8; j++)
                    v[j] = (start + j < BL) ? masked[start + j] : (MASK_ID + 1);
            }
            int hits[8];
            int cnt = 0;
            #pragma unroll
            for (int j = 0; j < 8; j++)
                if (v[j] == MASK_ID) hits[cnt++] = start + j;

            int inc = cnt;
            #pragma unroll
            for (int o = 1; o < 32; o <<= 1) {
                int t = __shfl_up_sync(0xffffffffu, inc, o);
                if (lane >= o) inc += t;
            }
            if (lane == 31) wtot[wid] = inc;
            __syncthreads();
            if (wid == 0) {
                int t = (lane < NT / 32) ? wtot[lane] : 0;
                #pragma unroll
                for (int o = 1; o < 32; o <<= 1) {
                    int u = __shfl_up_sync(0xffffffffu, t, o);
                    if (lane >= o) t += u;
                }
                if (lane < NT / 32) wtot[lane] = t;
            }
            __syncthreads();
            int excl = sbase + inc - cnt + (wid > 0 ? wtot[wid - 1] : 0);
            for (int k = 0; k < cnt; k++) {
                int o = excl + k;
                if (o < N && o < MAXN) {
                    int pos = hits[k];
                    g_mrow[o] = pos >> 7;
                    g_mcol[o] = pos & (L_SEQ - 1);
                }
            }
            __syncthreads();
            if (tid == 0) sbase += wtot[NT / 32 - 1];
            __syncthreads();
        }
        __threadfence();
        __syncthreads();
        if (tid == 0) atomicExch(&g_flag, 1);
        return;
    }

    // ================= row blocks =================
    const int r = blockIdx.x - 1;
    if (r >= N) return;
    const float* __restrict__ row = pred + (size_t)r * (size_t)C;

    // ---- streaming branchless shifted logsumexp + plain sum ----
    // float4 via __ldcs (evict-first), unrolled x4 (MLP=4).
    float s0 = 0.f, s1 = 0.f, s2 = 0.f, s3 = 0.f;
    float m0 = 0.f, m1 = 0.f, m2 = 0.f, m3 = 0.f;

    const int head = (int)(((16u - ((unsigned)(size_t)row & 15u)) & 15u) >> 2);
    if (tid < head) {
        float x = row[tid];
        s0 += __expf(x - SHIFT); m0 += x;
    }
    const float4* __restrict__ r4 = (const float4*)(row + head);
    const int n4   = (C - head) >> 2;
    const int tail = C - head - (n4 << 2);
    int i = tid;
    for (; i + 3 * NT < n4; i += 4 * NT) {
        float4 v0 = __ldcs(r4 + i);
        float4 v1 = __ldcs(r4 + i + NT);
        float4 v2 = __ldcs(r4 + i + 2 * NT);
        float4 v3 = __ldcs(r4 + i + 3 * NT);
        s0 += __expf(v0.x - SHIFT); m0 += v0.x;
        s1 += __expf(v0.y - SHIFT); m1 += v0.y;
        s2 += __expf(v0.z - SHIFT); m2 += v0.z;
        s3 += __expf(v0.w - SHIFT); m3 += v0.w;
        s0 += __expf(v1.x - SHIFT); m0 += v1.x;
        s1 += __expf(v1.y - SHIFT); m1 += v1.y;
        s2 += __expf(v1.z - SHIFT); m2 += v1.z;
        s3 += __expf(v1.w - SHIFT); m3 += v1.w;
        s0 += __expf(v2.x - SHIFT); m0 += v2.x;
        s1 += __expf(v2.y - SHIFT); m1 += v2.y;
        s2 += __expf(v2.z - SHIFT); m2 += v2.z;
        s3 += __expf(v2.w - SHIFT); m3 += v2.w;
        s0 += __expf(v3.x - SHIFT); m0 += v3.x;
        s1 += __expf(v3.y - SHIFT); m1 += v3.y;
        s2 += __expf(v3.z - SHIFT); m2 += v3.z;
        s3 += __expf(v3.w - SHIFT); m3 += v3.w;
    }
    for (; i < n4; i += NT) {
        float4 v = __ldcs(r4 + i);
        s0 += __expf(v.x - SHIFT); m0 += v.x;
        s1 += __expf(v.y - SHIFT); m1 += v.y;
        s2 += __expf(v.z - SHIFT); m2 += v.z;
        s3 += __expf(v.w - SHIFT); m3 += v.w;
    }
    if (tid < tail) {
        float x = row[head + (n4 << 2) + tid];
        s0 += __expf(x - SHIFT); m0 += x;
    }
    float s   = (s0 + s1) + (s2 + s3);
    float sum = (m0 + m1) + (m2 + m3);

    #pragma unroll
    for (int o = 16; o > 0; o >>= 1) {
        s   += __shfl_xor_sync(0xffffffffu, s, o);
        sum += __shfl_xor_sync(0xffffffffu, sum, o);
    }
    if (lane == 0) { red_a[wid] = s; red_b[wid] = sum; }

    // ---- wait for mask table (released ~6us in; we arrive much later) ----
    if (tid == 0) {
        while (atomicAdd(&g_flag, 0) == 0) __nanosleep(64);
    }
    __syncthreads();

    if (wid == 0) {
        float a = (lane < NT / 32) ? red_a[lane] : 0.f;
        float d = (lane < NT / 32) ? red_b[lane] : 0.f;
        #pragma unroll
        for (int o = 16; o > 0; o >>= 1) {
            a += __shfl_xor_sync(0xffffffffu, a, o);
            d += __shfl_xor_sync(0xffffffffu, d, o);
        }
        if (lane == 0) { sh_logZ = SHIFT + logf(a); sh_rowsum = d; }
    }

    const int b = g_mrow[r];
    const int c = g_mcol[r];

    // ---- per-position negative-target weights (faithful to reference) ----
    if (tid < L_SEQ) {
        float a = attn[b * L_SEQ + tid];
        float t = (float)tok_ids[b * L_SEQ + tid];
        sh_ai[tid] = a * t;
        sh_w[tid]  = a;
    }
    __syncthreads();
    const float center = sh_ai[c];
    if (tid < L_SEQ) {
        float a    = sh_w[tid];
        float negw = a - ((sh_ai[tid] == center) ? 1.f : 0.f);
        sh_negw[tid] = negw;
        sh_negc[tid] = sh_ai[tid] * negw;
    }
    __syncthreads();
    if (tid < L_SEQ) {
        float wfin, candf;
        if (c > 0) {
            float prev = sh_negc[c - 1];
            int   jm   = (tid - 1 + L_SEQ) & (L_SEQ - 1);
            float nm   = (sh_negc[jm] == prev) ? 1.f : 0.f;
            float nw2  = sh_negw[tid] * (1.f + nm);
            wfin  = nw2;
            candf = sh_ai[tid] * ((nw2 != 0.f) ? 1.f : 0.f);
        } else {
            wfin  = sh_negw[tid];
            candf = sh_negc[tid];
        }
        sh_w[tid]    = wfin;
        sh_cand[tid] = (int)candf;
    }
    __syncthreads();

    const float logZ = sh_logZ;

    // ---- unlikelihood gather (PRECISION-CRITICAL: precise expf/logf) ----
    float u = 0.f;
    if (tid < L_SEQ) {
        float w = sh_w[tid];
        if (w != 0.f) {
            int   idx = sh_cand[tid];
            float lp  = row[idx] - logZ;
            float omp = fmaxf(1.f - expf(lp), 1e-5f);
            u = -logf(omp) * w;
        }
    }
    #pragma unroll
    for (int o = 16; o > 0; o >>= 1)
        u += __shfl_xor_sync(0xffffffffu, u, o);
    if (lane == 0) red_a[wid] = u;
    __syncthreads();

    if (tid == 0) {
        float ut = 0.f;
        #pragma unroll
        for (int k = 0; k < NT / 32; k++) ut += red_a[k];
        g_unl[r] = ut;
        int   tgt = target[r];
        float lpt = row[tgt] - logZ;
        float sumlogp = sh_rowsum - (float)C * logZ;
        float epsw = SMOOTH_F / (float)(C - 1);
        float conf = 1.f - SMOOTH_F;
        float l = -(epsw * sumlogp + (conf - epsw) * lpt);
        float w = weight[tgt];
        g_mle[r] = l * w;
        g_wgt[r] = w;
        __threadfence();
        int ticket = atomicAdd(&g_done, 1);
        sh_last = (ticket == N - 1) ? 1 : 0;
    }
    __syncthreads();

    // ================= last row block: inline final reduction =================
    if (sh_last) {
        __threadfence();  // acquire: all g_* writes visible
        __shared__ double sm[NT], sw[NT], su[NT];
        double a = 0.0, w = 0.0, u2 = 0.0;
        for (int k = tid; k < N; k += NT) {
            a  += (double)g_mle[k];
            w  += (double)g_wgt[k];
            u2 += (double)g_unl[k];
        }
        sm[tid] = a; sw[tid] = w; su[tid] = u2;
        __syncthreads();
        for (int o = NT >> 1; o > 0; o >>= 1) {
            if (tid < o) { sm[tid] += sm[tid + o]; sw[tid] += sw[tid + o]; su[tid] += su[tid + o]; }
            __syncthreads();
        }
        if (tid == 0) {
            double mle  = sm[0] / sw[0];
            double unl  = su[0] / (double)N;
            double loss = mle + unl;   // RANK_ALPHA = 1.0
            if (out_size > 0) out[0] = (float)loss;
            if (out_size > 1) out[1] = (float)mle;
            if (out_size > 2) out[2] = (float)unl;
            for (int k = 3; k < out_size; k++) out[k] = 0.f;
            g_flag = 0;
            g_done = 0;
        }
    }
}

// ---------------- launch ----------------
extern "C" void kernel_launch(void* const* d_in, const int* in_sizes, int n_in,
                              void* d_out, int out_size)
{
    const float* pred   = (const float*)d_in[0];
    const int*   target = (const int*)  d_in[1];
    const int*   tok    = (const int*)  d_in[2];
    const float* attn   = (const float*)d_in[3];
    const int*   masked = (const int*)  d_in[4];
    const float* weight = (const float*)d_in[5];

    int N  = in_sizes[1];
    int C  = in_sizes[5];
    int BL = in_sizes[4];

    row_kernel<<<N + 1, NT>>>(pred, target, tok, attn, weight, masked,
                              (float*)d_out, C, N, BL, out_size);
}